// round 2
// baseline (speedup 1.0000x reference)
#include <cuda_runtime.h>

#define N_NODES 50000
#define N_EDGES 800000
#define N_RELS  500
#define HID     128
#define NH      8
#define NB      64
#define SLOPE   0.2f
#define SROW    132   // padded shared row stride (floats), keeps 16B align, kills bank conflicts
#define NPB     32    // nodes per block in k_node

// -------- static device scratch --------
__device__ float g_feat[(size_t)N_NODES * HID];
__device__ float g_h1[(size_t)N_NODES * HID];
__device__ float g_el[N_NODES * NH];
__device__ float g_er[N_NODES * NH];
__device__ float g_denomA[N_NODES * NH];
__device__ float g_ex[(size_t)N_EDGES * NH];
__device__ int   g_E1[N_EDGES];
__device__ int   g_E2[N_EDGES];
__device__ int   g_listN0[N_NODES];
__device__ int   g_listN1[N_NODES];
__device__ unsigned char g_maskS2[N_NODES];
__device__ unsigned char g_maskN1[N_NODES];
__device__ unsigned char g_maskN0[N_NODES];
__device__ int   g_b_of_node[N_NODES];
__device__ int   g_cnt[4];                 // 0:|E2| 1:|E1| 2:|N0| 3:|N1|
__device__ float g_rproj[2 * N_RELS * HID];
__device__ float g_ee[2 * N_RELS * NH];

// -------- helpers --------
__device__ __forceinline__ unsigned long long dup2(float x) {
    unsigned long long r;
    asm("mov.b64 %0, {%1, %1};" : "=l"(r) : "f"(x));
    return r;
}
__device__ __forceinline__ void ffma2(unsigned long long& d,
                                      unsigned long long a, unsigned long long b) {
    asm("fma.rn.f32x2 %0, %1, %2, %0;" : "+l"(d) : "l"(a), "l"(b));
}
__device__ __forceinline__ void unpack2(unsigned long long v, float& lo, float& hi) {
    asm("mov.b64 {%0, %1}, %2;" : "=f"(lo), "=f"(hi) : "l"(v));
}

// warp-aggregated slot reservation: one atomic per warp, only if warp has work
__device__ __forceinline__ int warp_reserve(int c, int* counter, int lane) {
    int pre = c;
#pragma unroll
    for (int off = 1; off < 32; off <<= 1) {
        int v = __shfl_up_sync(0xffffffffu, pre, off);
        if (lane >= off) pre += v;
    }
    int total = __shfl_sync(0xffffffffu, pre, 31);
    int base = 0;
    if (lane == 31 && total) base = atomicAdd(counter, total);
    base = __shfl_sync(0xffffffffu, base, 31);
    return base + pre - c;   // exclusive start for this thread's c items
}

// -------- kernels --------
__global__ void k_init(float* dout) {
    int i = blockIdx.x * blockDim.x + threadIdx.x;
    if (i < N_NODES) { g_maskS2[i] = 0; g_maskN1[i] = 0; g_maskN0[i] = 0; }
    if (i < NB * HID) dout[i] = 0.0f;
    if (i < 4)        g_cnt[i] = 0;
}

__global__ void k_seed(const int* __restrict__ offs) {
    int t = threadIdx.x;
    if (t < NB) {
        int n = offs[t];
        g_maskS2[n] = 1;
        g_maskN1[n] = 1;
        g_b_of_node[n] = t;
    }
}

// layer-2 edge filter: dst in S2 (4 edges/thread, warp-aggregated)
__global__ void k_filter2(const int4* __restrict__ src4, const int4* __restrict__ dst4) {
    int i = blockIdx.x * blockDim.x + threadIdx.x;
    int lane = threadIdx.x & 31;
    unsigned m = 0;
    int4 d, s;
    if (i < N_EDGES / 4) {
        d = __ldg(&dst4[i]);
        m |= g_maskS2[d.x] ? 1u : 0u;
        m |= g_maskS2[d.y] ? 2u : 0u;
        m |= g_maskS2[d.z] ? 4u : 0u;
        m |= g_maskS2[d.w] ? 8u : 0u;
    }
    int c = __popc(m);
    int pos = warp_reserve(c, &g_cnt[0], lane);
    if (m) {
        s = __ldg(&src4[i]);
        if (m & 1u) { g_E2[pos++] = 4 * i + 0; g_maskN1[s.x] = 1; }
        if (m & 2u) { g_E2[pos++] = 4 * i + 1; g_maskN1[s.y] = 1; }
        if (m & 4u) { g_E2[pos++] = 4 * i + 2; g_maskN1[s.z] = 1; }
        if (m & 8u) { g_E2[pos++] = 4 * i + 3; g_maskN1[s.w] = 1; }
    }
}

// layer-1 edge filter: dst in N1
__global__ void k_filter1(const int4* __restrict__ src4, const int4* __restrict__ dst4) {
    int i = blockIdx.x * blockDim.x + threadIdx.x;
    int lane = threadIdx.x & 31;
    unsigned m = 0;
    int4 d, s;
    if (i < N_EDGES / 4) {
        d = __ldg(&dst4[i]);
        m |= g_maskN1[d.x] ? 1u : 0u;
        m |= g_maskN1[d.y] ? 2u : 0u;
        m |= g_maskN1[d.z] ? 4u : 0u;
        m |= g_maskN1[d.w] ? 8u : 0u;
    }
    int c = __popc(m);
    int pos = warp_reserve(c, &g_cnt[1], lane);
    if (m) {
        s = __ldg(&src4[i]);
        if (m & 1u) { g_E1[pos++] = 4 * i + 0; g_maskN0[s.x] = 1; }
        if (m & 2u) { g_E1[pos++] = 4 * i + 1; g_maskN0[s.y] = 1; }
        if (m & 4u) { g_E1[pos++] = 4 * i + 2; g_maskN0[s.z] = 1; }
        if (m & 8u) { g_E1[pos++] = 4 * i + 3; g_maskN0[s.w] = 1; }
    }
}

// node-list compaction + zero layer-1 accumulators for N1 nodes
__global__ void k_compact() {
    int i = blockIdx.x * blockDim.x + threadIdx.x;
    int lane = threadIdx.x & 31;
    int in0 = 0, in1 = 0;
    if (i < N_NODES) {
        unsigned char m1 = g_maskN1[i];
        in1 = m1 ? 1 : 0;
        in0 = (g_maskN0[i] | m1) ? 1 : 0;
    }
    int p0 = warp_reserve(in0, &g_cnt[2], lane);
    int p1 = warp_reserve(in1, &g_cnt[3], lane);
    if (in0) g_listN0[p0] = i;
    if (in1) {
        g_listN1[p1] = i;
        float4 z = make_float4(0.f, 0.f, 0.f, 0.f);
        float4* row = (float4*)(g_h1 + (size_t)i * HID);
#pragma unroll
        for (int q = 0; q < HID / 4; q++) row[q] = z;
        ((float4*)(g_denomA + i * NH))[0] = z;
        ((float4*)(g_denomA + i * NH))[1] = z;
    }
}

// relation projection + relation attention scores (both layers)
__global__ void k_rel(const float* __restrict__ rel_table,
                      const float* __restrict__ W_rel,
                      const float* __restrict__ attn_e) {
    __shared__ float s[HID];
    int b = blockIdx.x;            // b = l*N_RELS + r
    int l = b / N_RELS;
    int r = b % N_RELS;
    int j = threadIdx.x;
    s[j] = rel_table[r * HID + j];
    __syncthreads();
    const float* W = W_rel + (size_t)l * HID * HID;
    float acc = 0.0f;
#pragma unroll
    for (int k = 0; k < HID; k++) acc += s[k] * __ldg(&W[k * HID + j]);
    g_rproj[(size_t)b * HID + j] = acc;
    float v = acc * attn_e[l * HID + j];
    v += __shfl_xor_sync(0xffffffffu, v, 8);
    v += __shfl_xor_sync(0xffffffffu, v, 4);
    v += __shfl_xor_sync(0xffffffffu, v, 2);
    v += __shfl_xor_sync(0xffffffffu, v, 1);
    if ((j & 15) == 0) g_ee[b * NH + (j >> 4)] = v;
}

// node projection + el/er; register-tiled, f32x2 packed FMA.
// blockDim=256: ct = tid&15 owns 8 cols, nt = tid>>4 owns 2 nodes (32 nodes/block)
__global__ void k_node(int layer,
                       const float* __restrict__ ent_table,
                       const int*   __restrict__ ent_ids,
                       const float* __restrict__ W_ent,
                       const float* __restrict__ attn_l,
                       const float* __restrict__ attn_r) {
    __shared__ float s[NPB * SROW];
    int tid = threadIdx.x;
    int ct = tid & 15, nt = tid >> 4;
    int c0 = ct * 8;
    int cnt = (layer == 0) ? g_cnt[2] : g_cnt[3];
    const int* list = (layer == 0) ? g_listN0 : g_listN1;
    const float* W = W_ent + (size_t)layer * HID * HID;

    float alv[8], arv[8];
#pragma unroll
    for (int q = 0; q < 8; q++) {
        alv[q] = attn_l[layer * HID + c0 + q];
        arv[q] = attn_r[layer * HID + c0 + q];
    }

    for (int base = blockIdx.x * NPB; base < cnt; base += gridDim.x * NPB) {
        __syncthreads();
        for (int idx = tid; idx < NPB * (HID / 4); idx += 256) {
            int r = idx >> 5;        // row 0..31
            int q = idx & 31;        // float4 index 0..31
            int gi = base + r;
            float4 v = make_float4(0.f, 0.f, 0.f, 0.f);
            if (gi < cnt) {
                int n = list[gi];
                const float* row = (layer == 0)
                    ? (ent_table + (size_t)__ldg(&ent_ids[n]) * HID)
                    : (g_h1 + (size_t)n * HID);
                v = *(const float4*)(row + 4 * q);
            }
            *(float4*)&s[r * SROW + 4 * q] = v;
        }
        __syncthreads();

        unsigned long long acc[2][4];
#pragma unroll
        for (int n = 0; n < 2; n++)
#pragma unroll
            for (int p = 0; p < 4; p++) acc[n][p] = 0ull;

        int n0 = nt * 2, n1 = nt * 2 + 1;
#pragma unroll 8
        for (int k = 0; k < HID; k++) {
            ulonglong2 w01 = *(const ulonglong2*)(W + (size_t)k * HID + c0);
            ulonglong2 w23 = *(const ulonglong2*)(W + (size_t)k * HID + c0 + 4);
            unsigned long long d0 = dup2(s[n0 * SROW + k]);
            unsigned long long d1 = dup2(s[n1 * SROW + k]);
            ffma2(acc[0][0], d0, w01.x); ffma2(acc[0][1], d0, w01.y);
            ffma2(acc[0][2], d0, w23.x); ffma2(acc[0][3], d0, w23.y);
            ffma2(acc[1][0], d1, w01.x); ffma2(acc[1][1], d1, w01.y);
            ffma2(acc[1][2], d1, w23.x); ffma2(acc[1][3], d1, w23.y);
        }

#pragma unroll
        for (int n = 0; n < 2; n++) {
            float f[8];
#pragma unroll
            for (int p = 0; p < 4; p++) unpack2(acc[n][p], f[2 * p], f[2 * p + 1]);
            float pl = 0.f, pr = 0.f;
#pragma unroll
            for (int q = 0; q < 8; q++) { pl += f[q] * alv[q]; pr += f[q] * arv[q]; }
            // combine the two col-threads (ct pairs) that share head h = ct>>1
            pl += __shfl_xor_sync(0xffffffffu, pl, 1);
            pr += __shfl_xor_sync(0xffffffffu, pr, 1);
            int gi = base + nt * 2 + n;
            if (gi < cnt) {
                int node = list[gi];
                float* fr = g_feat + (size_t)node * HID + c0;
                *(float4*)fr       = make_float4(f[0], f[1], f[2], f[3]);
                *(float4*)(fr + 4) = make_float4(f[4], f[5], f[6], f[7]);
                if ((ct & 1) == 0) {
                    g_el[node * NH + (ct >> 1)] = pl;
                    g_er[node * NH + (ct >> 1)] = pr;
                }
            }
        }
    }
}

// layer-0 edge scores + denom
__global__ void k_score0(const int* __restrict__ src,
                         const int* __restrict__ dst,
                         const int* __restrict__ rel_ids) {
    int cnt = g_cnt[1];
    int t = blockIdx.x * blockDim.x + threadIdx.x;
    int h = t & 7;
    int e0 = t >> 3;
    int stride = (gridDim.x * blockDim.x) >> 3;
    for (int e = e0; e < cnt; e += stride) {
        int ei = g_E1[e];
        int s = __ldg(&src[ei]), d = __ldg(&dst[ei]), r = __ldg(&rel_ids[ei]);
        float v = g_el[s * NH + h] + g_er[d * NH + h] + g_ee[r * NH + h];
        v = (v > 0.0f) ? v : SLOPE * v;
        float ex = expf(v);
        g_ex[(size_t)e * NH + h] = ex;
        atomicAdd(&g_denomA[d * NH + h], ex);
    }
}

// layer-0 aggregation into g_h1
__global__ void k_agg0(const int* __restrict__ src,
                       const int* __restrict__ dst,
                       const int* __restrict__ rel_ids) {
    int cnt = g_cnt[1];
    int t = blockIdx.x * blockDim.x + threadIdx.x;
    int j = t & 31;
    int e0 = t >> 5;
    int stride = (gridDim.x * blockDim.x) >> 5;
    for (int e = e0; e < cnt; e += stride) {
        int ei = g_E1[e];
        int s = __ldg(&src[ei]), d = __ldg(&dst[ei]), r = __ldg(&rel_ids[ei]);
        int h = j >> 2;
        float alpha = g_ex[(size_t)e * NH + h] / g_denomA[d * NH + h];
        float4 f  = *(const float4*)(g_feat  + (size_t)s * HID + 4 * j);
        float4 rp = *(const float4*)(g_rproj + (size_t)r * HID + 4 * j);
        float* ob = g_h1 + (size_t)d * HID;
        atomicAdd(ob + 4 * j + 0, (f.x + rp.x) * alpha);
        atomicAdd(ob + 4 * j + 1, (f.y + rp.y) * alpha);
        atomicAdd(ob + 4 * j + 2, (f.z + rp.z) * alpha);
        atomicAdd(ob + 4 * j + 3, (f.w + rp.w) * alpha);
    }
}

// layer-2: fused score + softmax-denominator + aggregation, single block.
__global__ void k_l2edges(const int* __restrict__ src,
                          const int* __restrict__ dst,
                          const int* __restrict__ rel_ids,
                          float* __restrict__ dout) {
    __shared__ float sden[NB * NH];
    int tid = threadIdx.x;          // 1024 threads
    int cnt = g_cnt[0];
    for (int i = tid; i < NB * NH; i += 1024) sden[i] = 0.0f;
    __syncthreads();

    int h = tid & 7, e0 = tid >> 3;
    for (int e = e0; e < cnt; e += 128) {
        int ei = g_E2[e];
        int s = src[ei], d = dst[ei], r = rel_ids[ei];
        float v = g_el[s * NH + h] + g_er[d * NH + h]
                + g_ee[(N_RELS + r) * NH + h];
        v = (v > 0.0f) ? v : SLOPE * v;
        float ex = expf(v);
        g_ex[(size_t)e * NH + h] = ex;
        atomicAdd(&sden[g_b_of_node[d] * NH + h], ex);
    }
    __syncthreads();

    int j = tid & 31, ee0 = tid >> 5;
    for (int e = ee0; e < cnt; e += 32) {
        int ei = g_E2[e];
        int s = src[ei], d = dst[ei], r = rel_ids[ei];
        int b = g_b_of_node[d];
        int hh = j >> 2;
        float alpha = g_ex[(size_t)e * NH + hh] / sden[b * NH + hh];
        float4 f  = *(const float4*)(g_feat  + (size_t)s * HID + 4 * j);
        float4 rp = *(const float4*)(g_rproj + (size_t)(N_RELS + r) * HID + 4 * j);
        float* ob = dout + (size_t)b * HID;
        atomicAdd(ob + 4 * j + 0, (f.x + rp.x) * alpha);
        atomicAdd(ob + 4 * j + 1, (f.y + rp.y) * alpha);
        atomicAdd(ob + 4 * j + 2, (f.z + rp.z) * alpha);
        atomicAdd(ob + 4 * j + 3, (f.w + rp.w) * alpha);
    }
}

// -------- launch --------
extern "C" void kernel_launch(void* const* d_in, const int* in_sizes, int n_in,
                              void* d_out, int out_size) {
    const float* ent_table = (const float*)d_in[0];
    const float* rel_table = (const float*)d_in[1];
    const float* W_ent     = (const float*)d_in[2];
    const float* W_rel     = (const float*)d_in[3];
    const float* attn_l    = (const float*)d_in[4];
    const float* attn_r    = (const float*)d_in[5];
    const float* attn_e    = (const float*)d_in[6];
    const int*   ent_ids   = (const int*)d_in[7];
    const int*   rel_ids   = (const int*)d_in[8];
    const int*   src       = (const int*)d_in[9];
    const int*   dst       = (const int*)d_in[10];
    const int*   goffs     = (const int*)d_in[11];
    float*       out       = (float*)d_out;

    k_init<<<(N_NODES + 255) / 256, 256>>>(out);
    k_seed<<<1, 64>>>(goffs);
    k_filter2<<<(N_EDGES / 4 + 255) / 256, 256>>>((const int4*)src, (const int4*)dst);
    k_filter1<<<(N_EDGES / 4 + 255) / 256, 256>>>((const int4*)src, (const int4*)dst);
    k_compact<<<(N_NODES + 255) / 256, 256>>>();
    k_rel<<<2 * N_RELS, 128>>>(rel_table, W_rel, attn_e);

    k_node<<<512, 256>>>(0, ent_table, ent_ids, W_ent, attn_l, attn_r);
    k_score0<<<512, 256>>>(src, dst, rel_ids);
    k_agg0<<<1024, 256>>>(src, dst, rel_ids);

    k_node<<<64, 256>>>(1, ent_table, ent_ids, W_ent, attn_l, attn_r);
    k_l2edges<<<1, 1024>>>(src, dst, rel_ids, out);
}

// round 3
// speedup vs baseline: 1.0683x; 1.0683x over previous
#include <cuda_runtime.h>

#define N_NODES 50000
#define N_EDGES 800000
#define N_RELS  500
#define HID     128
#define NH      8
#define NB      64
#define SLOPE   0.2f
#define NW      ((N_NODES + 31) / 32)   // bitmask words

// -------- static device scratch --------
__device__ float g_feat[(size_t)N_NODES * HID];
__device__ float g_h1[(size_t)N_NODES * HID];
__device__ float g_el[N_NODES * NH];
__device__ float g_er[N_NODES * NH];
__device__ float g_denomA[N_NODES * NH];
__device__ float g_ex[(size_t)N_EDGES * NH];
__device__ int   g_E1[N_EDGES];
__device__ int   g_E2[N_EDGES];
__device__ int   g_listN0[N_NODES];
__device__ int   g_listN1[N_NODES];
__device__ unsigned g_bmS2[NW];
__device__ unsigned g_bmN1[NW];
__device__ unsigned g_bmN0[NW];
__device__ int   g_b_of_node[N_NODES];
__device__ int   g_cnt[4];                 // 0:|E2| 1:|E1| 2:|N0| 3:|N1|
__device__ float g_rproj[2 * N_RELS * HID];
__device__ float g_ee[2 * N_RELS * NH];

// -------- helpers --------
__device__ __forceinline__ int warp_reserve(int c, int* counter, int lane) {
    int pre = c;
#pragma unroll
    for (int off = 1; off < 32; off <<= 1) {
        int v = __shfl_up_sync(0xffffffffu, pre, off);
        if (lane >= off) pre += v;
    }
    int total = __shfl_sync(0xffffffffu, pre, 31);
    int base = 0;
    if (lane == 31 && total) base = atomicAdd(counter, total);
    base = __shfl_sync(0xffffffffu, base, 31);
    return base + pre - c;
}
__device__ __forceinline__ int bit_test(const unsigned* bm, int n) {
    return (bm[n >> 5] >> (n & 31)) & 1;
}

// -------- kernels --------
__global__ void k_init(float* dout) {
    int i = blockIdx.x * blockDim.x + threadIdx.x;
    if (i < NW) { g_bmS2[i] = 0u; g_bmN1[i] = 0u; g_bmN0[i] = 0u; }
    if (i < NB * HID) dout[i] = 0.0f;
    if (i < 4) g_cnt[i] = 0;
}

__global__ void k_seed(const int* __restrict__ offs) {
    int t = threadIdx.x;
    if (t < NB) {
        int n = offs[t];
        atomicOr(&g_bmS2[n >> 5], 1u << (n & 31));
        atomicOr(&g_bmN1[n >> 5], 1u << (n & 31));
        g_b_of_node[n] = t;
    }
}

// layer-2 edge filter: dst in S2. Two int4 chunks (8 edges) per thread for MLP.
__global__ void k_filter2(const int4* __restrict__ src4, const int4* __restrict__ dst4) {
    const int half = N_EDGES / 8;          // 100000
    int base = blockIdx.x * blockDim.x + threadIdx.x;
    int lane = threadIdx.x & 31;
    unsigned m0 = 0, m1 = 0;
    int4 d0, d1;
    if (base < half) {
        int i0 = base, i1 = base + half;
        d0 = __ldg(&dst4[i0]);
        d1 = __ldg(&dst4[i1]);
        unsigned w0 = g_bmS2[d0.x >> 5], w1 = g_bmS2[d0.y >> 5];
        unsigned w2 = g_bmS2[d0.z >> 5], w3 = g_bmS2[d0.w >> 5];
        unsigned w4 = g_bmS2[d1.x >> 5], w5 = g_bmS2[d1.y >> 5];
        unsigned w6 = g_bmS2[d1.z >> 5], w7 = g_bmS2[d1.w >> 5];
        m0 = ((w0 >> (d0.x & 31)) & 1u) | (((w1 >> (d0.y & 31)) & 1u) << 1)
           | (((w2 >> (d0.z & 31)) & 1u) << 2) | (((w3 >> (d0.w & 31)) & 1u) << 3);
        m1 = ((w4 >> (d1.x & 31)) & 1u) | (((w5 >> (d1.y & 31)) & 1u) << 1)
           | (((w6 >> (d1.z & 31)) & 1u) << 2) | (((w7 >> (d1.w & 31)) & 1u) << 3);
    }
    int c = __popc(m0) + __popc(m1);
    int pos = warp_reserve(c, &g_cnt[0], lane);
    if (m0) {
        int i0 = base;
        int4 s = __ldg(&src4[i0]);
        if (m0 & 1u) { g_E2[pos++] = 4 * i0 + 0; atomicOr(&g_bmN1[s.x >> 5], 1u << (s.x & 31)); }
        if (m0 & 2u) { g_E2[pos++] = 4 * i0 + 1; atomicOr(&g_bmN1[s.y >> 5], 1u << (s.y & 31)); }
        if (m0 & 4u) { g_E2[pos++] = 4 * i0 + 2; atomicOr(&g_bmN1[s.z >> 5], 1u << (s.z & 31)); }
        if (m0 & 8u) { g_E2[pos++] = 4 * i0 + 3; atomicOr(&g_bmN1[s.w >> 5], 1u << (s.w & 31)); }
    }
    if (m1) {
        int i1 = base + half;
        int4 s = __ldg(&src4[i1]);
        if (m1 & 1u) { g_E2[pos++] = 4 * i1 + 0; atomicOr(&g_bmN1[s.x >> 5], 1u << (s.x & 31)); }
        if (m1 & 2u) { g_E2[pos++] = 4 * i1 + 1; atomicOr(&g_bmN1[s.y >> 5], 1u << (s.y & 31)); }
        if (m1 & 4u) { g_E2[pos++] = 4 * i1 + 2; atomicOr(&g_bmN1[s.z >> 5], 1u << (s.z & 31)); }
        if (m1 & 8u) { g_E2[pos++] = 4 * i1 + 3; atomicOr(&g_bmN1[s.w >> 5], 1u << (s.w & 31)); }
    }
}

// layer-1 edge filter: dst in N1
__global__ void k_filter1(const int4* __restrict__ src4, const int4* __restrict__ dst4) {
    const int half = N_EDGES / 8;
    int base = blockIdx.x * blockDim.x + threadIdx.x;
    int lane = threadIdx.x & 31;
    unsigned m0 = 0, m1 = 0;
    int4 d0, d1;
    if (base < half) {
        int i0 = base, i1 = base + half;
        d0 = __ldg(&dst4[i0]);
        d1 = __ldg(&dst4[i1]);
        unsigned w0 = g_bmN1[d0.x >> 5], w1 = g_bmN1[d0.y >> 5];
        unsigned w2 = g_bmN1[d0.z >> 5], w3 = g_bmN1[d0.w >> 5];
        unsigned w4 = g_bmN1[d1.x >> 5], w5 = g_bmN1[d1.y >> 5];
        unsigned w6 = g_bmN1[d1.z >> 5], w7 = g_bmN1[d1.w >> 5];
        m0 = ((w0 >> (d0.x & 31)) & 1u) | (((w1 >> (d0.y & 31)) & 1u) << 1)
           | (((w2 >> (d0.z & 31)) & 1u) << 2) | (((w3 >> (d0.w & 31)) & 1u) << 3);
        m1 = ((w4 >> (d1.x & 31)) & 1u) | (((w5 >> (d1.y & 31)) & 1u) << 1)
           | (((w6 >> (d1.z & 31)) & 1u) << 2) | (((w7 >> (d1.w & 31)) & 1u) << 3);
    }
    int c = __popc(m0) + __popc(m1);
    int pos = warp_reserve(c, &g_cnt[1], lane);
    if (m0) {
        int i0 = base;
        int4 s = __ldg(&src4[i0]);
        if (m0 & 1u) { g_E1[pos++] = 4 * i0 + 0; atomicOr(&g_bmN0[s.x >> 5], 1u << (s.x & 31)); }
        if (m0 & 2u) { g_E1[pos++] = 4 * i0 + 1; atomicOr(&g_bmN0[s.y >> 5], 1u << (s.y & 31)); }
        if (m0 & 4u) { g_E1[pos++] = 4 * i0 + 2; atomicOr(&g_bmN0[s.z >> 5], 1u << (s.z & 31)); }
        if (m0 & 8u) { g_E1[pos++] = 4 * i0 + 3; atomicOr(&g_bmN0[s.w >> 5], 1u << (s.w & 31)); }
    }
    if (m1) {
        int i1 = base + half;
        int4 s = __ldg(&src4[i1]);
        if (m1 & 1u) { g_E1[pos++] = 4 * i1 + 0; atomicOr(&g_bmN0[s.x >> 5], 1u << (s.x & 31)); }
        if (m1 & 2u) { g_E1[pos++] = 4 * i1 + 1; atomicOr(&g_bmN0[s.y >> 5], 1u << (s.y & 31)); }
        if (m1 & 4u) { g_E1[pos++] = 4 * i1 + 2; atomicOr(&g_bmN0[s.z >> 5], 1u << (s.z & 31)); }
        if (m1 & 8u) { g_E1[pos++] = 4 * i1 + 3; atomicOr(&g_bmN0[s.w >> 5], 1u << (s.w & 31)); }
    }
}

// node-list compaction + zero layer-1 accumulators for N1 nodes
__global__ void k_compact() {
    int i = blockIdx.x * blockDim.x + threadIdx.x;
    int lane = threadIdx.x & 31;
    int in0 = 0, in1 = 0;
    if (i < N_NODES) {
        in1 = bit_test(g_bmN1, i);
        in0 = bit_test(g_bmN0, i) | in1;
    }
    int p0 = warp_reserve(in0, &g_cnt[2], lane);
    int p1 = warp_reserve(in1, &g_cnt[3], lane);
    if (in0) g_listN0[p0] = i;
    if (in1) {
        g_listN1[p1] = i;
        float4 z = make_float4(0.f, 0.f, 0.f, 0.f);
        float4* row = (float4*)(g_h1 + (size_t)i * HID);
#pragma unroll
        for (int q = 0; q < HID / 4; q++) row[q] = z;
        ((float4*)(g_denomA + i * NH))[0] = z;
        ((float4*)(g_denomA + i * NH))[1] = z;
    }
}

// relation projection + relation attention scores (both layers)
__global__ void k_rel(const float* __restrict__ rel_table,
                      const float* __restrict__ W_rel,
                      const float* __restrict__ attn_e) {
    __shared__ float s[HID];
    int b = blockIdx.x;            // b = l*N_RELS + r
    int l = b / N_RELS;
    int r = b % N_RELS;
    int j = threadIdx.x;
    s[j] = rel_table[r * HID + j];
    __syncthreads();
    const float* W = W_rel + (size_t)l * HID * HID;
    float acc = 0.0f;
#pragma unroll
    for (int k = 0; k < HID; k++) acc += s[k] * __ldg(&W[k * HID + j]);
    g_rproj[(size_t)b * HID + j] = acc;
    float v = acc * attn_e[l * HID + j];
    v += __shfl_xor_sync(0xffffffffu, v, 8);
    v += __shfl_xor_sync(0xffffffffu, v, 4);
    v += __shfl_xor_sync(0xffffffffu, v, 2);
    v += __shfl_xor_sync(0xffffffffu, v, 1);
    if ((j & 15) == 0) g_ee[b * NH + (j >> 4)] = v;
}

// node projection + el/er (round-1 known-good formulation)
__global__ void k_node(int layer,
                       const float* __restrict__ ent_table,
                       const int*   __restrict__ ent_ids,
                       const float* __restrict__ W_ent,
                       const float* __restrict__ attn_l,
                       const float* __restrict__ attn_r) {
    __shared__ float s[HID];
    int j = threadIdx.x;
    int cnt = (layer == 0) ? g_cnt[2] : g_cnt[3];
    const int* list = (layer == 0) ? g_listN0 : g_listN1;
    const float* W = W_ent + (size_t)layer * HID * HID;
    float al = attn_l[layer * HID + j];
    float ar = attn_r[layer * HID + j];
    for (int idx = blockIdx.x; idx < cnt; idx += gridDim.x) {
        int n = list[idx];
        const float* row = (layer == 0)
            ? (ent_table + (size_t)__ldg(&ent_ids[n]) * HID)
            : (g_h1 + (size_t)n * HID);
        __syncthreads();
        s[j] = row[j];
        __syncthreads();
        float acc = 0.0f;
#pragma unroll
        for (int k = 0; k < HID; k++) acc += s[k] * __ldg(&W[k * HID + j]);
        g_feat[(size_t)n * HID + j] = acc;
        float v = acc * al;
        v += __shfl_xor_sync(0xffffffffu, v, 8);
        v += __shfl_xor_sync(0xffffffffu, v, 4);
        v += __shfl_xor_sync(0xffffffffu, v, 2);
        v += __shfl_xor_sync(0xffffffffu, v, 1);
        if ((j & 15) == 0) g_el[n * NH + (j >> 4)] = v;
        float w = acc * ar;
        w += __shfl_xor_sync(0xffffffffu, w, 8);
        w += __shfl_xor_sync(0xffffffffu, w, 4);
        w += __shfl_xor_sync(0xffffffffu, w, 2);
        w += __shfl_xor_sync(0xffffffffu, w, 1);
        if ((j & 15) == 0) g_er[n * NH + (j >> 4)] = w;
    }
}

// layer-0 edge scores + denom
__global__ void k_score0(const int* __restrict__ src,
                         const int* __restrict__ dst,
                         const int* __restrict__ rel_ids) {
    int cnt = g_cnt[1];
    int t = blockIdx.x * blockDim.x + threadIdx.x;
    int h = t & 7;
    int e0 = t >> 3;
    int stride = (gridDim.x * blockDim.x) >> 3;
    for (int e = e0; e < cnt; e += stride) {
        int ei = g_E1[e];
        int s = __ldg(&src[ei]), d = __ldg(&dst[ei]), r = __ldg(&rel_ids[ei]);
        float v = g_el[s * NH + h] + g_er[d * NH + h] + g_ee[r * NH + h];
        v = (v > 0.0f) ? v : SLOPE * v;
        float ex = expf(v);
        g_ex[(size_t)e * NH + h] = ex;
        atomicAdd(&g_denomA[d * NH + h], ex);
    }
}

// layer-0 aggregation into g_h1
__global__ void k_agg0(const int* __restrict__ src,
                       const int* __restrict__ dst,
                       const int* __restrict__ rel_ids) {
    int cnt = g_cnt[1];
    int t = blockIdx.x * blockDim.x + threadIdx.x;
    int j = t & 31;
    int e0 = t >> 5;
    int stride = (gridDim.x * blockDim.x) >> 5;
    for (int e = e0; e < cnt; e += stride) {
        int ei = g_E1[e];
        int s = __ldg(&src[ei]), d = __ldg(&dst[ei]), r = __ldg(&rel_ids[ei]);
        int h = j >> 2;
        float alpha = g_ex[(size_t)e * NH + h] / g_denomA[d * NH + h];
        float4 f  = *(const float4*)(g_feat  + (size_t)s * HID + 4 * j);
        float4 rp = *(const float4*)(g_rproj + (size_t)r * HID + 4 * j);
        float* ob = g_h1 + (size_t)d * HID;
        atomicAdd(ob + 4 * j + 0, (f.x + rp.x) * alpha);
        atomicAdd(ob + 4 * j + 1, (f.y + rp.y) * alpha);
        atomicAdd(ob + 4 * j + 2, (f.z + rp.z) * alpha);
        atomicAdd(ob + 4 * j + 3, (f.w + rp.w) * alpha);
    }
}

// layer-2: fused score + softmax-denominator + aggregation, single block.
__global__ void k_l2edges(const int* __restrict__ src,
                          const int* __restrict__ dst,
                          const int* __restrict__ rel_ids,
                          float* __restrict__ dout) {
    __shared__ float sden[NB * NH];
    int tid = threadIdx.x;          // 1024 threads
    int cnt = g_cnt[0];
    for (int i = tid; i < NB * NH; i += 1024) sden[i] = 0.0f;
    __syncthreads();

    int h = tid & 7, e0 = tid >> 3;
    for (int e = e0; e < cnt; e += 128) {
        int ei = g_E2[e];
        int s = src[ei], d = dst[ei], r = rel_ids[ei];
        float v = g_el[s * NH + h] + g_er[d * NH + h]
                + g_ee[(N_RELS + r) * NH + h];
        v = (v > 0.0f) ? v : SLOPE * v;
        float ex = expf(v);
        g_ex[(size_t)e * NH + h] = ex;
        atomicAdd(&sden[g_b_of_node[d] * NH + h], ex);
    }
    __syncthreads();

    int j = tid & 31, ee0 = tid >> 5;
    for (int e = ee0; e < cnt; e += 32) {
        int ei = g_E2[e];
        int s = src[ei], d = dst[ei], r = rel_ids[ei];
        int b = g_b_of_node[d];
        int hh = j >> 2;
        float alpha = g_ex[(size_t)e * NH + hh] / sden[b * NH + hh];
        float4 f  = *(const float4*)(g_feat  + (size_t)s * HID + 4 * j);
        float4 rp = *(const float4*)(g_rproj + (size_t)(N_RELS + r) * HID + 4 * j);
        float* ob = dout + (size_t)b * HID;
        atomicAdd(ob + 4 * j + 0, (f.x + rp.x) * alpha);
        atomicAdd(ob + 4 * j + 1, (f.y + rp.y) * alpha);
        atomicAdd(ob + 4 * j + 2, (f.z + rp.z) * alpha);
        atomicAdd(ob + 4 * j + 3, (f.w + rp.w) * alpha);
    }
}

// -------- launch --------
extern "C" void kernel_launch(void* const* d_in, const int* in_sizes, int n_in,
                              void* d_out, int out_size) {
    const float* ent_table = (const float*)d_in[0];
    const float* rel_table = (const float*)d_in[1];
    const float* W_ent     = (const float*)d_in[2];
    const float* W_rel     = (const float*)d_in[3];
    const float* attn_l    = (const float*)d_in[4];
    const float* attn_r    = (const float*)d_in[5];
    const float* attn_e    = (const float*)d_in[6];
    const int*   ent_ids   = (const int*)d_in[7];
    const int*   rel_ids   = (const int*)d_in[8];
    const int*   src       = (const int*)d_in[9];
    const int*   dst       = (const int*)d_in[10];
    const int*   goffs     = (const int*)d_in[11];
    float*       out       = (float*)d_out;

    k_init<<<32, 256>>>(out);
    k_seed<<<1, 64>>>(goffs);
    k_filter2<<<(N_EDGES / 8 + 255) / 256, 256>>>((const int4*)src, (const int4*)dst);
    k_filter1<<<(N_EDGES / 8 + 255) / 256, 256>>>((const int4*)src, (const int4*)dst);
    k_compact<<<(N_NODES + 255) / 256, 256>>>();
    k_rel<<<2 * N_RELS, 128>>>(rel_table, W_rel, attn_e);

    k_node<<<2048, 128>>>(0, ent_table, ent_ids, W_ent, attn_l, attn_r);
    k_score0<<<512, 256>>>(src, dst, rel_ids);
    k_agg0<<<512, 256>>>(src, dst, rel_ids);

    k_node<<<2048, 128>>>(1, ent_table, ent_ids, W_ent, attn_l, attn_r);
    k_l2edges<<<1, 1024>>>(src, dst, rel_ids, out);
}

// round 4
// speedup vs baseline: 1.5537x; 1.4544x over previous
#include <cuda_runtime.h>

#define N_NODES 50000
#define N_EDGES 800000
#define N_RELS  500
#define HID     128
#define NH      8
#define NB      64
#define SLOPE   0.2f
#define NW      ((N_NODES + 31) / 32)   // bitmask words

// -------- static device scratch --------
__device__ float g_feat[(size_t)N_NODES * HID];
__device__ float g_h1[(size_t)N_NODES * HID];
__device__ float g_el[N_NODES * NH];
__device__ float g_er[N_NODES * NH];
__device__ float g_denomA[N_NODES * NH];
__device__ float g_denomB[NB * NH];
__device__ float g_ex[(size_t)N_EDGES * NH];
__device__ int   g_E1[N_EDGES];
__device__ int   g_E2[N_EDGES];
__device__ int   g_listN0[N_NODES];
__device__ int   g_listN1[N_NODES];
__device__ unsigned g_bmS2[NW];
__device__ unsigned g_bmN1[NW];
__device__ unsigned g_bmN0[NW];
__device__ int   g_b_of_node[N_NODES];
__device__ int   g_cnt[4];                 // 0:|E2| 1:|E1| 2:|N0| 3:|N1|
__device__ float g_rproj[2 * N_RELS * HID];
__device__ float g_ee[2 * N_RELS * NH];

// -------- helpers --------
__device__ __forceinline__ int warp_reserve(int c, int* counter, int lane) {
    int pre = c;
#pragma unroll
    for (int off = 1; off < 32; off <<= 1) {
        int v = __shfl_up_sync(0xffffffffu, pre, off);
        if (lane >= off) pre += v;
    }
    int total = __shfl_sync(0xffffffffu, pre, 31);
    int base = 0;
    if (lane == 31 && total) base = atomicAdd(counter, total);
    base = __shfl_sync(0xffffffffu, base, 31);
    return base + pre - c;
}
__device__ __forceinline__ int bit_test(const unsigned* bm, int n) {
    return (bm[n >> 5] >> (n & 31)) & 1;
}

// -------- kernels --------
__global__ void k_init(float* dout) {
    int i = blockIdx.x * blockDim.x + threadIdx.x;
    if (i < NW) { g_bmS2[i] = 0u; g_bmN1[i] = 0u; g_bmN0[i] = 0u; }
    if (i < NB * HID) dout[i] = 0.0f;
    if (i < NB * NH)  g_denomB[i] = 0.0f;
    if (i < 4) g_cnt[i] = 0;
}

__global__ void k_seed(const int* __restrict__ offs) {
    int t = threadIdx.x;
    if (t < NB) {
        int n = offs[t];
        atomicOr(&g_bmS2[n >> 5], 1u << (n & 31));
        atomicOr(&g_bmN1[n >> 5], 1u << (n & 31));
        g_b_of_node[n] = t;
    }
}

// layer-2 edge filter: dst in S2. Two int4 chunks (8 edges) per thread.
__global__ void k_filter2(const int4* __restrict__ src4, const int4* __restrict__ dst4) {
    const int half = N_EDGES / 8;
    int base = blockIdx.x * blockDim.x + threadIdx.x;
    int lane = threadIdx.x & 31;
    unsigned m0 = 0, m1 = 0;
    if (base < half) {
        int4 d0 = __ldg(&dst4[base]);
        int4 d1 = __ldg(&dst4[base + half]);
        unsigned w0 = g_bmS2[d0.x >> 5], w1 = g_bmS2[d0.y >> 5];
        unsigned w2 = g_bmS2[d0.z >> 5], w3 = g_bmS2[d0.w >> 5];
        unsigned w4 = g_bmS2[d1.x >> 5], w5 = g_bmS2[d1.y >> 5];
        unsigned w6 = g_bmS2[d1.z >> 5], w7 = g_bmS2[d1.w >> 5];
        m0 = ((w0 >> (d0.x & 31)) & 1u) | (((w1 >> (d0.y & 31)) & 1u) << 1)
           | (((w2 >> (d0.z & 31)) & 1u) << 2) | (((w3 >> (d0.w & 31)) & 1u) << 3);
        m1 = ((w4 >> (d1.x & 31)) & 1u) | (((w5 >> (d1.y & 31)) & 1u) << 1)
           | (((w6 >> (d1.z & 31)) & 1u) << 2) | (((w7 >> (d1.w & 31)) & 1u) << 3);
    }
    int c = __popc(m0) + __popc(m1);
    int pos = warp_reserve(c, &g_cnt[0], lane);
    if (m0) {
        int i0 = base;
        int4 s = __ldg(&src4[i0]);
        if (m0 & 1u) { g_E2[pos++] = 4 * i0 + 0; atomicOr(&g_bmN1[s.x >> 5], 1u << (s.x & 31)); }
        if (m0 & 2u) { g_E2[pos++] = 4 * i0 + 1; atomicOr(&g_bmN1[s.y >> 5], 1u << (s.y & 31)); }
        if (m0 & 4u) { g_E2[pos++] = 4 * i0 + 2; atomicOr(&g_bmN1[s.z >> 5], 1u << (s.z & 31)); }
        if (m0 & 8u) { g_E2[pos++] = 4 * i0 + 3; atomicOr(&g_bmN1[s.w >> 5], 1u << (s.w & 31)); }
    }
    if (m1) {
        int i1 = base + half;
        int4 s = __ldg(&src4[i1]);
        if (m1 & 1u) { g_E2[pos++] = 4 * i1 + 0; atomicOr(&g_bmN1[s.x >> 5], 1u << (s.x & 31)); }
        if (m1 & 2u) { g_E2[pos++] = 4 * i1 + 1; atomicOr(&g_bmN1[s.y >> 5], 1u << (s.y & 31)); }
        if (m1 & 4u) { g_E2[pos++] = 4 * i1 + 2; atomicOr(&g_bmN1[s.z >> 5], 1u << (s.z & 31)); }
        if (m1 & 8u) { g_E2[pos++] = 4 * i1 + 3; atomicOr(&g_bmN1[s.w >> 5], 1u << (s.w & 31)); }
    }
}

// layer-1 edge filter: dst in N1
__global__ void k_filter1(const int4* __restrict__ src4, const int4* __restrict__ dst4) {
    const int half = N_EDGES / 8;
    int base = blockIdx.x * blockDim.x + threadIdx.x;
    int lane = threadIdx.x & 31;
    unsigned m0 = 0, m1 = 0;
    if (base < half) {
        int4 d0 = __ldg(&dst4[base]);
        int4 d1 = __ldg(&dst4[base + half]);
        unsigned w0 = g_bmN1[d0.x >> 5], w1 = g_bmN1[d0.y >> 5];
        unsigned w2 = g_bmN1[d0.z >> 5], w3 = g_bmN1[d0.w >> 5];
        unsigned w4 = g_bmN1[d1.x >> 5], w5 = g_bmN1[d1.y >> 5];
        unsigned w6 = g_bmN1[d1.z >> 5], w7 = g_bmN1[d1.w >> 5];
        m0 = ((w0 >> (d0.x & 31)) & 1u) | (((w1 >> (d0.y & 31)) & 1u) << 1)
           | (((w2 >> (d0.z & 31)) & 1u) << 2) | (((w3 >> (d0.w & 31)) & 1u) << 3);
        m1 = ((w4 >> (d1.x & 31)) & 1u) | (((w5 >> (d1.y & 31)) & 1u) << 1)
           | (((w6 >> (d1.z & 31)) & 1u) << 2) | (((w7 >> (d1.w & 31)) & 1u) << 3);
    }
    int c = __popc(m0) + __popc(m1);
    int pos = warp_reserve(c, &g_cnt[1], lane);
    if (m0) {
        int i0 = base;
        int4 s = __ldg(&src4[i0]);
        if (m0 & 1u) { g_E1[pos++] = 4 * i0 + 0; atomicOr(&g_bmN0[s.x >> 5], 1u << (s.x & 31)); }
        if (m0 & 2u) { g_E1[pos++] = 4 * i0 + 1; atomicOr(&g_bmN0[s.y >> 5], 1u << (s.y & 31)); }
        if (m0 & 4u) { g_E1[pos++] = 4 * i0 + 2; atomicOr(&g_bmN0[s.z >> 5], 1u << (s.z & 31)); }
        if (m0 & 8u) { g_E1[pos++] = 4 * i0 + 3; atomicOr(&g_bmN0[s.w >> 5], 1u << (s.w & 31)); }
    }
    if (m1) {
        int i1 = base + half;
        int4 s = __ldg(&src4[i1]);
        if (m1 & 1u) { g_E1[pos++] = 4 * i1 + 0; atomicOr(&g_bmN0[s.x >> 5], 1u << (s.x & 31)); }
        if (m1 & 2u) { g_E1[pos++] = 4 * i1 + 1; atomicOr(&g_bmN0[s.y >> 5], 1u << (s.y & 31)); }
        if (m1 & 4u) { g_E1[pos++] = 4 * i1 + 2; atomicOr(&g_bmN0[s.z >> 5], 1u << (s.z & 31)); }
        if (m1 & 8u) { g_E1[pos++] = 4 * i1 + 3; atomicOr(&g_bmN0[s.w >> 5], 1u << (s.w & 31)); }
    }
}

// node-list compaction (no zeroing here — k_zero1 does it in parallel)
__global__ void k_compact() {
    int i = blockIdx.x * blockDim.x + threadIdx.x;
    int lane = threadIdx.x & 31;
    int in0 = 0, in1 = 0;
    if (i < N_NODES) {
        in1 = bit_test(g_bmN1, i);
        in0 = bit_test(g_bmN0, i) | in1;
    }
    int p0 = warp_reserve(in0, &g_cnt[2], lane);
    int p1 = warp_reserve(in1, &g_cnt[3], lane);
    if (in0) g_listN0[p0] = i;
    if (in1) g_listN1[p1] = i;
}

// zero layer-1 accumulators at N1 nodes only (parallel over columns)
__global__ void k_zero1() {
    int j = threadIdx.x;
    int cnt = g_cnt[3];
    for (int idx = blockIdx.x; idx < cnt; idx += gridDim.x) {
        int n = g_listN1[idx];
        g_h1[(size_t)n * HID + j] = 0.0f;
        if (j < NH) g_denomA[n * NH + j] = 0.0f;
    }
}

// relation projection + relation attention scores (both layers)
__global__ void k_rel(const float* __restrict__ rel_table,
                      const float* __restrict__ W_rel,
                      const float* __restrict__ attn_e) {
    __shared__ float s[HID];
    int b = blockIdx.x;            // b = l*N_RELS + r
    int l = b / N_RELS;
    int r = b % N_RELS;
    int j = threadIdx.x;
    s[j] = rel_table[r * HID + j];
    __syncthreads();
    const float* W = W_rel + (size_t)l * HID * HID;
    float acc = 0.0f;
#pragma unroll
    for (int k = 0; k < HID; k++) acc += s[k] * W[k * HID + j];
    g_rproj[(size_t)b * HID + j] = acc;
    float v = acc * attn_e[l * HID + j];
    v += __shfl_xor_sync(0xffffffffu, v, 8);
    v += __shfl_xor_sync(0xffffffffu, v, 4);
    v += __shfl_xor_sync(0xffffffffu, v, 2);
    v += __shfl_xor_sync(0xffffffffu, v, 1);
    if ((j & 15) == 0) g_ee[b * NH + (j >> 4)] = v;
}

// node projection + el/er (round-1 known-good formulation)
__global__ void k_node(int layer,
                       const float* __restrict__ ent_table,
                       const int*   __restrict__ ent_ids,
                       const float* __restrict__ W_ent,
                       const float* __restrict__ attn_l,
                       const float* __restrict__ attn_r) {
    __shared__ float s[HID];
    int j = threadIdx.x;
    int cnt = (layer == 0) ? g_cnt[2] : g_cnt[3];
    const int* list = (layer == 0) ? g_listN0 : g_listN1;
    const float* W = W_ent + (size_t)layer * HID * HID;
    float al = attn_l[layer * HID + j];
    float ar = attn_r[layer * HID + j];
    for (int idx = blockIdx.x; idx < cnt; idx += gridDim.x) {
        int n = list[idx];
        const float* row = (layer == 0)
            ? (ent_table + (size_t)ent_ids[n] * HID)
            : (g_h1 + (size_t)n * HID);
        __syncthreads();
        s[j] = row[j];
        __syncthreads();
        float acc = 0.0f;
#pragma unroll
        for (int k = 0; k < HID; k++) acc += s[k] * W[k * HID + j];
        g_feat[(size_t)n * HID + j] = acc;
        float v = acc * al;
        v += __shfl_xor_sync(0xffffffffu, v, 8);
        v += __shfl_xor_sync(0xffffffffu, v, 4);
        v += __shfl_xor_sync(0xffffffffu, v, 2);
        v += __shfl_xor_sync(0xffffffffu, v, 1);
        if ((j & 15) == 0) g_el[n * NH + (j >> 4)] = v;
        float w = acc * ar;
        w += __shfl_xor_sync(0xffffffffu, w, 8);
        w += __shfl_xor_sync(0xffffffffu, w, 4);
        w += __shfl_xor_sync(0xffffffffu, w, 2);
        w += __shfl_xor_sync(0xffffffffu, w, 1);
        if ((j & 15) == 0) g_er[n * NH + (j >> 4)] = w;
    }
}

// edge scores: ex = exp(leakyrelu(el[src]+er[dst]+ee[rel])), accumulate denom
__global__ void k_score(int layer,
                        const int* __restrict__ src,
                        const int* __restrict__ dst,
                        const int* __restrict__ rel_ids) {
    int cnt = (layer == 0) ? g_cnt[1] : g_cnt[0];
    const int* El = (layer == 0) ? g_E1 : g_E2;
    int t = blockIdx.x * blockDim.x + threadIdx.x;
    int h = t & 7;
    int e0 = t >> 3;
    int stride = (gridDim.x * blockDim.x) >> 3;
    for (int e = e0; e < cnt; e += stride) {
        int ei = El[e];
        int s = src[ei], d = dst[ei], r = rel_ids[ei];
        float v = g_el[s * NH + h] + g_er[d * NH + h]
                + g_ee[(layer * N_RELS + r) * NH + h];
        v = (v > 0.0f) ? v : SLOPE * v;
        float ex = expf(v);
        g_ex[(size_t)e * NH + h] = ex;
        if (layer == 0) atomicAdd(&g_denomA[d * NH + h], ex);
        else            atomicAdd(&g_denomB[g_b_of_node[d] * NH + h], ex);
    }
}

// aggregation: out[dst] += (feat[src] + rproj[rel]) * alpha
__global__ void k_agg(int layer,
                      const int* __restrict__ src,
                      const int* __restrict__ dst,
                      const int* __restrict__ rel_ids,
                      float* __restrict__ dout) {
    int cnt = (layer == 0) ? g_cnt[1] : g_cnt[0];
    const int* El = (layer == 0) ? g_E1 : g_E2;
    int t = blockIdx.x * blockDim.x + threadIdx.x;
    int j = t & 31;
    int e0 = t >> 5;
    int stride = (gridDim.x * blockDim.x) >> 5;
    for (int e = e0; e < cnt; e += stride) {
        int ei = El[e];
        int s = src[ei], d = dst[ei], r = rel_ids[ei];
        int h = j >> 2;
        float den = (layer == 0) ? g_denomA[d * NH + h]
                                 : g_denomB[g_b_of_node[d] * NH + h];
        float alpha = g_ex[(size_t)e * NH + h] / den;
        float4 f  = *(const float4*)(g_feat  + (size_t)s * HID + 4 * j);
        float4 rp = *(const float4*)(g_rproj + (size_t)(layer * N_RELS + r) * HID + 4 * j);
        float* ob = (layer == 0) ? (g_h1 + (size_t)d * HID)
                                 : (dout + (size_t)g_b_of_node[d] * HID);
        atomicAdd(ob + 4 * j + 0, (f.x + rp.x) * alpha);
        atomicAdd(ob + 4 * j + 1, (f.y + rp.y) * alpha);
        atomicAdd(ob + 4 * j + 2, (f.z + rp.z) * alpha);
        atomicAdd(ob + 4 * j + 3, (f.w + rp.w) * alpha);
    }
}

// -------- launch --------
extern "C" void kernel_launch(void* const* d_in, const int* in_sizes, int n_in,
                              void* d_out, int out_size) {
    const float* ent_table = (const float*)d_in[0];
    const float* rel_table = (const float*)d_in[1];
    const float* W_ent     = (const float*)d_in[2];
    const float* W_rel     = (const float*)d_in[3];
    const float* attn_l    = (const float*)d_in[4];
    const float* attn_r    = (const float*)d_in[5];
    const float* attn_e    = (const float*)d_in[6];
    const int*   ent_ids   = (const int*)d_in[7];
    const int*   rel_ids   = (const int*)d_in[8];
    const int*   src       = (const int*)d_in[9];
    const int*   dst       = (const int*)d_in[10];
    const int*   goffs     = (const int*)d_in[11];
    float*       out       = (float*)d_out;

    k_init<<<32, 256>>>(out);
    k_seed<<<1, 64>>>(goffs);
    k_filter2<<<(N_EDGES / 8 + 255) / 256, 256>>>((const int4*)src, (const int4*)dst);
    k_filter1<<<(N_EDGES / 8 + 255) / 256, 256>>>((const int4*)src, (const int4*)dst);
    k_compact<<<(N_NODES + 255) / 256, 256>>>();
    k_rel<<<2 * N_RELS, 128>>>(rel_table, W_rel, attn_e);
    k_zero1<<<1024, 128>>>();

    // layer 0 (full frontier N0)
    k_node<<<2048, 128>>>(0, ent_table, ent_ids, W_ent, attn_l, attn_r);
    k_score<<<512, 256>>>(0, src, dst, rel_ids);
    k_agg<<<512, 256>>>(0, src, dst, rel_ids, out);

    // layer 1 (frontier N1, output rows only)
    k_node<<<2048, 128>>>(1, ent_table, ent_ids, W_ent, attn_l, attn_r);
    k_score<<<64, 256>>>(1, src, dst, rel_ids);
    k_agg<<<64, 256>>>(1, src, dst, rel_ids, out);
}

// round 5
// speedup vs baseline: 1.8733x; 1.2057x over previous
#include <cuda_runtime.h>

#define N_NODES 50000
#define N_EDGES 800000
#define N_RELS  500
#define HID     128
#define NH      8
#define NB      64
#define SLOPE   0.2f
#define NW      ((N_NODES + 31) / 32)   // bitmask words
#define NPB     8                       // nodes per block in k_node

// -------- static device scratch --------
__device__ float g_feat[(size_t)N_NODES * HID];
__device__ float g_h1[(size_t)N_NODES * HID];
__device__ float g_el[N_NODES * NH];
__device__ float g_er[N_NODES * NH];
__device__ float g_denomA[N_NODES * NH];
__device__ float g_denomB[NB * NH];
__device__ float g_ex[(size_t)N_EDGES * NH];
__device__ int4  g_E1[N_EDGES];            // {src, dst, rel, 0}
__device__ int4  g_E2[N_EDGES];            // {src, dst, rel, batch}
__device__ int   g_listN0[N_NODES];
__device__ int   g_listN1[N_NODES];
__device__ unsigned g_bmS2[NW];
__device__ unsigned g_bmN1[NW];
__device__ unsigned g_bmN0[NW];
__device__ int   g_b_of_node[N_NODES];
__device__ int   g_cnt[4];                 // 0:|E2| 1:|E1| 2:|N0| 3:|N1|
__device__ float g_rproj[2 * N_RELS * HID];
__device__ float g_ee[2 * N_RELS * NH];

// -------- helpers --------
__device__ __forceinline__ int warp_reserve(int c, int* counter, int lane) {
    int pre = c;
#pragma unroll
    for (int off = 1; off < 32; off <<= 1) {
        int v = __shfl_up_sync(0xffffffffu, pre, off);
        if (lane >= off) pre += v;
    }
    int total = __shfl_sync(0xffffffffu, pre, 31);
    int base = 0;
    if (lane == 31 && total) base = atomicAdd(counter, total);
    base = __shfl_sync(0xffffffffu, base, 31);
    return base + pre - c;
}
__device__ __forceinline__ int bit_test(const unsigned* bm, int n) {
    return (bm[n >> 5] >> (n & 31)) & 1;
}
__device__ __forceinline__ void ffma2(unsigned long long& d,
                                      unsigned long long a, unsigned long long b) {
    asm("fma.rn.f32x2 %0, %1, %2, %0;" : "+l"(d) : "l"(a), "l"(b));
}
__device__ __forceinline__ void unpack2(unsigned long long v, float& lo, float& hi) {
    asm("mov.b64 {%0, %1}, %2;" : "=f"(lo), "=f"(hi) : "l"(v));
}

// -------- kernels --------
// init everything + seed, single block (saves a launch; __syncthreads orders it)
__global__ void k_init(float* dout, const int* __restrict__ offs) {
    int tid = threadIdx.x;  // 1024
    for (int i = tid; i < NW; i += 1024) { g_bmS2[i] = 0u; g_bmN1[i] = 0u; g_bmN0[i] = 0u; }
    for (int i = tid; i < NB * HID; i += 1024) dout[i] = 0.0f;
    if (tid < NB * NH) g_denomB[tid] = 0.0f;
    if (tid < 4) g_cnt[tid] = 0;
    __syncthreads();
    if (tid < NB) {
        int n = offs[tid];
        atomicOr(&g_bmS2[n >> 5], 1u << (n & 31));
        atomicOr(&g_bmN1[n >> 5], 1u << (n & 31));
        g_b_of_node[n] = tid;
    }
}

// layer-2 edge filter: dst in S2. Two int4 chunks (8 edges) per thread.
__global__ void k_filter2(const int4* __restrict__ src4, const int4* __restrict__ dst4,
                          const int* __restrict__ rel_ids) {
    const int half = N_EDGES / 8;
    int base = blockIdx.x * blockDim.x + threadIdx.x;
    int lane = threadIdx.x & 31;
    unsigned m0 = 0, m1 = 0;
    int4 d0, d1;
    if (base < half) {
        d0 = __ldg(&dst4[base]);
        d1 = __ldg(&dst4[base + half]);
        unsigned w0 = g_bmS2[d0.x >> 5], w1 = g_bmS2[d0.y >> 5];
        unsigned w2 = g_bmS2[d0.z >> 5], w3 = g_bmS2[d0.w >> 5];
        unsigned w4 = g_bmS2[d1.x >> 5], w5 = g_bmS2[d1.y >> 5];
        unsigned w6 = g_bmS2[d1.z >> 5], w7 = g_bmS2[d1.w >> 5];
        m0 = ((w0 >> (d0.x & 31)) & 1u) | (((w1 >> (d0.y & 31)) & 1u) << 1)
           | (((w2 >> (d0.z & 31)) & 1u) << 2) | (((w3 >> (d0.w & 31)) & 1u) << 3);
        m1 = ((w4 >> (d1.x & 31)) & 1u) | (((w5 >> (d1.y & 31)) & 1u) << 1)
           | (((w6 >> (d1.z & 31)) & 1u) << 2) | (((w7 >> (d1.w & 31)) & 1u) << 3);
    }
    int c = __popc(m0) + __popc(m1);
    int pos = warp_reserve(c, &g_cnt[0], lane);
    if (m0) {
        int i0 = base;
        int4 s = __ldg(&src4[i0]);
        if (m0 & 1u) { g_E2[pos++] = make_int4(s.x, d0.x, __ldg(&rel_ids[4*i0+0]), g_b_of_node[d0.x]); atomicOr(&g_bmN1[s.x >> 5], 1u << (s.x & 31)); }
        if (m0 & 2u) { g_E2[pos++] = make_int4(s.y, d0.y, __ldg(&rel_ids[4*i0+1]), g_b_of_node[d0.y]); atomicOr(&g_bmN1[s.y >> 5], 1u << (s.y & 31)); }
        if (m0 & 4u) { g_E2[pos++] = make_int4(s.z, d0.z, __ldg(&rel_ids[4*i0+2]), g_b_of_node[d0.z]); atomicOr(&g_bmN1[s.z >> 5], 1u << (s.z & 31)); }
        if (m0 & 8u) { g_E2[pos++] = make_int4(s.w, d0.w, __ldg(&rel_ids[4*i0+3]), g_b_of_node[d0.w]); atomicOr(&g_bmN1[s.w >> 5], 1u << (s.w & 31)); }
    }
    if (m1) {
        int i1 = base + half;
        int4 s = __ldg(&src4[i1]);
        if (m1 & 1u) { g_E2[pos++] = make_int4(s.x, d1.x, __ldg(&rel_ids[4*i1+0]), g_b_of_node[d1.x]); atomicOr(&g_bmN1[s.x >> 5], 1u << (s.x & 31)); }
        if (m1 & 2u) { g_E2[pos++] = make_int4(s.y, d1.y, __ldg(&rel_ids[4*i1+1]), g_b_of_node[d1.y]); atomicOr(&g_bmN1[s.y >> 5], 1u << (s.y & 31)); }
        if (m1 & 4u) { g_E2[pos++] = make_int4(s.z, d1.z, __ldg(&rel_ids[4*i1+2]), g_b_of_node[d1.z]); atomicOr(&g_bmN1[s.z >> 5], 1u << (s.z & 31)); }
        if (m1 & 8u) { g_E2[pos++] = make_int4(s.w, d1.w, __ldg(&rel_ids[4*i1+3]), g_b_of_node[d1.w]); atomicOr(&g_bmN1[s.w >> 5], 1u << (s.w & 31)); }
    }
}

// layer-1 edge filter: dst in N1
__global__ void k_filter1(const int4* __restrict__ src4, const int4* __restrict__ dst4,
                          const int* __restrict__ rel_ids) {
    const int half = N_EDGES / 8;
    int base = blockIdx.x * blockDim.x + threadIdx.x;
    int lane = threadIdx.x & 31;
    unsigned m0 = 0, m1 = 0;
    int4 d0, d1;
    if (base < half) {
        d0 = __ldg(&dst4[base]);
        d1 = __ldg(&dst4[base + half]);
        unsigned w0 = g_bmN1[d0.x >> 5], w1 = g_bmN1[d0.y >> 5];
        unsigned w2 = g_bmN1[d0.z >> 5], w3 = g_bmN1[d0.w >> 5];
        unsigned w4 = g_bmN1[d1.x >> 5], w5 = g_bmN1[d1.y >> 5];
        unsigned w6 = g_bmN1[d1.z >> 5], w7 = g_bmN1[d1.w >> 5];
        m0 = ((w0 >> (d0.x & 31)) & 1u) | (((w1 >> (d0.y & 31)) & 1u) << 1)
           | (((w2 >> (d0.z & 31)) & 1u) << 2) | (((w3 >> (d0.w & 31)) & 1u) << 3);
        m1 = ((w4 >> (d1.x & 31)) & 1u) | (((w5 >> (d1.y & 31)) & 1u) << 1)
           | (((w6 >> (d1.z & 31)) & 1u) << 2) | (((w7 >> (d1.w & 31)) & 1u) << 3);
    }
    int c = __popc(m0) + __popc(m1);
    int pos = warp_reserve(c, &g_cnt[1], lane);
    if (m0) {
        int i0 = base;
        int4 s = __ldg(&src4[i0]);
        if (m0 & 1u) { g_E1[pos++] = make_int4(s.x, d0.x, __ldg(&rel_ids[4*i0+0]), 0); atomicOr(&g_bmN0[s.x >> 5], 1u << (s.x & 31)); }
        if (m0 & 2u) { g_E1[pos++] = make_int4(s.y, d0.y, __ldg(&rel_ids[4*i0+1]), 0); atomicOr(&g_bmN0[s.y >> 5], 1u << (s.y & 31)); }
        if (m0 & 4u) { g_E1[pos++] = make_int4(s.z, d0.z, __ldg(&rel_ids[4*i0+2]), 0); atomicOr(&g_bmN0[s.z >> 5], 1u << (s.z & 31)); }
        if (m0 & 8u) { g_E1[pos++] = make_int4(s.w, d0.w, __ldg(&rel_ids[4*i0+3]), 0); atomicOr(&g_bmN0[s.w >> 5], 1u << (s.w & 31)); }
    }
    if (m1) {
        int i1 = base + half;
        int4 s = __ldg(&src4[i1]);
        if (m1 & 1u) { g_E1[pos++] = make_int4(s.x, d1.x, __ldg(&rel_ids[4*i1+0]), 0); atomicOr(&g_bmN0[s.x >> 5], 1u << (s.x & 31)); }
        if (m1 & 2u) { g_E1[pos++] = make_int4(s.y, d1.y, __ldg(&rel_ids[4*i1+1]), 0); atomicOr(&g_bmN0[s.y >> 5], 1u << (s.y & 31)); }
        if (m1 & 4u) { g_E1[pos++] = make_int4(s.z, d1.z, __ldg(&rel_ids[4*i1+2]), 0); atomicOr(&g_bmN0[s.z >> 5], 1u << (s.z & 31)); }
        if (m1 & 8u) { g_E1[pos++] = make_int4(s.w, d1.w, __ldg(&rel_ids[4*i1+3]), 0); atomicOr(&g_bmN0[s.w >> 5], 1u << (s.w & 31)); }
    }
}

// node-list compaction + zero layer-1 accumulators for N1 nodes (merged)
__global__ void k_compact() {
    int i = blockIdx.x * blockDim.x + threadIdx.x;
    int lane = threadIdx.x & 31;
    int in0 = 0, in1 = 0;
    if (i < N_NODES) {
        in1 = bit_test(g_bmN1, i);
        in0 = bit_test(g_bmN0, i) | in1;
    }
    int p0 = warp_reserve(in0, &g_cnt[2], lane);
    int p1 = warp_reserve(in1, &g_cnt[3], lane);
    if (in0) g_listN0[p0] = i;
    if (in1) {
        g_listN1[p1] = i;
        float4 z = make_float4(0.f, 0.f, 0.f, 0.f);
        float4* row = (float4*)(g_h1 + (size_t)i * HID);
#pragma unroll
        for (int q = 0; q < HID / 4; q++) row[q] = z;
        ((float4*)(g_denomA + i * NH))[0] = z;
        ((float4*)(g_denomA + i * NH))[1] = z;
    }
}

// relation projection + relation attention scores (both layers)
__global__ void k_rel(const float* __restrict__ rel_table,
                      const float* __restrict__ W_rel,
                      const float* __restrict__ attn_e) {
    __shared__ float s[HID];
    int b = blockIdx.x;            // b = l*N_RELS + r
    int l = b / N_RELS;
    int r = b % N_RELS;
    int j = threadIdx.x;
    s[j] = rel_table[r * HID + j];
    __syncthreads();
    const float* W = W_rel + (size_t)l * HID * HID;
    float acc = 0.0f;
#pragma unroll
    for (int k = 0; k < HID; k++) acc += s[k] * W[k * HID + j];
    g_rproj[(size_t)b * HID + j] = acc;
    float v = acc * attn_e[l * HID + j];
    v += __shfl_xor_sync(0xffffffffu, v, 8);
    v += __shfl_xor_sync(0xffffffffu, v, 4);
    v += __shfl_xor_sync(0xffffffffu, v, 2);
    v += __shfl_xor_sync(0xffffffffu, v, 1);
    if ((j & 15) == 0) g_ee[b * NH + (j >> 4)] = v;
}

// node projection + el/er. 8 nodes/block, 128 threads.
// thread tid: column pair (2t, 2t+1) with t = tid&63, node group g = tid>>6 (4 nodes).
// f32x2 packed accumulators; s staged in shared pre-duplicated as float2{v,v}.
__global__ void k_node(int layer,
                       const float* __restrict__ ent_table,
                       const int*   __restrict__ ent_ids,
                       const float* __restrict__ W_ent,
                       const float* __restrict__ attn_l,
                       const float* __restrict__ attn_r) {
    __shared__ float2 s2[NPB][HID + 2];
    int tid = threadIdx.x;
    int t = tid & 63;
    int g = tid >> 6;
    int cnt = (layer == 0) ? g_cnt[2] : g_cnt[3];
    const int* list = (layer == 0) ? g_listN0 : g_listN1;
    const float* W = W_ent + (size_t)layer * HID * HID;
    float al0 = attn_l[layer * HID + 2 * t], al1 = attn_l[layer * HID + 2 * t + 1];
    float ar0 = attn_r[layer * HID + 2 * t], ar1 = attn_r[layer * HID + 2 * t + 1];

    for (int base = blockIdx.x * NPB; base < cnt; base += gridDim.x * NPB) {
        __syncthreads();
        for (int idx = tid; idx < NPB * 32; idx += 128) {
            int n = idx >> 5, q = idx & 31;
            float4 v = make_float4(0.f, 0.f, 0.f, 0.f);
            int gi = base + n;
            if (gi < cnt) {
                int node = list[gi];
                const float* row = (layer == 0)
                    ? (ent_table + (size_t)__ldg(&ent_ids[node]) * HID)
                    : (g_h1 + (size_t)node * HID);
                v = *(const float4*)(row + 4 * q);
            }
            s2[n][4 * q + 0] = make_float2(v.x, v.x);
            s2[n][4 * q + 1] = make_float2(v.y, v.y);
            s2[n][4 * q + 2] = make_float2(v.z, v.z);
            s2[n][4 * q + 3] = make_float2(v.w, v.w);
        }
        __syncthreads();

        unsigned long long acc0 = 0, acc1 = 0, acc2 = 0, acc3 = 0;
        int n0 = g * 4;
#pragma unroll 4
        for (int k = 0; k < HID; k += 4) {
            unsigned long long w0 = *(const unsigned long long*)(W + (size_t)(k + 0) * HID + 2 * t);
            unsigned long long w1 = *(const unsigned long long*)(W + (size_t)(k + 1) * HID + 2 * t);
            unsigned long long w2 = *(const unsigned long long*)(W + (size_t)(k + 2) * HID + 2 * t);
            unsigned long long w3 = *(const unsigned long long*)(W + (size_t)(k + 3) * HID + 2 * t);
            ffma2(acc0, *(const unsigned long long*)&s2[n0 + 0][k + 0], w0);
            ffma2(acc1, *(const unsigned long long*)&s2[n0 + 1][k + 0], w0);
            ffma2(acc2, *(const unsigned long long*)&s2[n0 + 2][k + 0], w0);
            ffma2(acc3, *(const unsigned long long*)&s2[n0 + 3][k + 0], w0);
            ffma2(acc0, *(const unsigned long long*)&s2[n0 + 0][k + 1], w1);
            ffma2(acc1, *(const unsigned long long*)&s2[n0 + 1][k + 1], w1);
            ffma2(acc2, *(const unsigned long long*)&s2[n0 + 2][k + 1], w1);
            ffma2(acc3, *(const unsigned long long*)&s2[n0 + 3][k + 1], w1);
            ffma2(acc0, *(const unsigned long long*)&s2[n0 + 0][k + 2], w2);
            ffma2(acc1, *(const unsigned long long*)&s2[n0 + 1][k + 2], w2);
            ffma2(acc2, *(const unsigned long long*)&s2[n0 + 2][k + 2], w2);
            ffma2(acc3, *(const unsigned long long*)&s2[n0 + 3][k + 2], w2);
            ffma2(acc0, *(const unsigned long long*)&s2[n0 + 0][k + 3], w3);
            ffma2(acc1, *(const unsigned long long*)&s2[n0 + 1][k + 3], w3);
            ffma2(acc2, *(const unsigned long long*)&s2[n0 + 2][k + 3], w3);
            ffma2(acc3, *(const unsigned long long*)&s2[n0 + 3][k + 3], w3);
        }

        unsigned long long accs[4] = {acc0, acc1, acc2, acc3};
#pragma unroll
        for (int n = 0; n < 4; n++) {
            float f0, f1;
            unpack2(accs[n], f0, f1);
            float pl = f0 * al0 + f1 * al1;
            float pr = f0 * ar0 + f1 * ar1;
            pl += __shfl_xor_sync(0xffffffffu, pl, 4);
            pl += __shfl_xor_sync(0xffffffffu, pl, 2);
            pl += __shfl_xor_sync(0xffffffffu, pl, 1);
            pr += __shfl_xor_sync(0xffffffffu, pr, 4);
            pr += __shfl_xor_sync(0xffffffffu, pr, 2);
            pr += __shfl_xor_sync(0xffffffffu, pr, 1);
            int gi = base + n0 + n;
            if (gi < cnt) {
                int node = list[gi];
                *(float2*)(g_feat + (size_t)node * HID + 2 * t) = make_float2(f0, f1);
                if ((t & 7) == 0) {
                    g_el[node * NH + (t >> 3)] = pl;
                    g_er[node * NH + (t >> 3)] = pr;
                }
            }
        }
    }
}

// edge scores: ex = exp(leakyrelu(el[src]+er[dst]+ee[rel])), accumulate denom
__global__ void k_score(int layer) {
    int cnt = (layer == 0) ? g_cnt[1] : g_cnt[0];
    const int4* El = (layer == 0) ? g_E1 : g_E2;
    int t = blockIdx.x * blockDim.x + threadIdx.x;
    int h = t & 7;
    int e0 = t >> 3;
    int stride = (gridDim.x * blockDim.x) >> 3;
    for (int e = e0; e < cnt; e += stride) {
        int4 p = El[e];
        float v = g_el[p.x * NH + h] + g_er[p.y * NH + h]
                + g_ee[(layer * N_RELS + p.z) * NH + h];
        v = (v > 0.0f) ? v : SLOPE * v;
        float ex = expf(v);
        g_ex[(size_t)e * NH + h] = ex;
        if (layer == 0) atomicAdd(&g_denomA[p.y * NH + h], ex);
        else            atomicAdd(&g_denomB[p.w * NH + h], ex);
    }
}

// aggregation: out[dst] += (feat[src] + rproj[rel]) * alpha
__global__ void k_agg(int layer, float* __restrict__ dout) {
    int cnt = (layer == 0) ? g_cnt[1] : g_cnt[0];
    const int4* El = (layer == 0) ? g_E1 : g_E2;
    int t = blockIdx.x * blockDim.x + threadIdx.x;
    int j = t & 31;
    int e0 = t >> 5;
    int stride = (gridDim.x * blockDim.x) >> 5;
    for (int e = e0; e < cnt; e += stride) {
        int4 p = El[e];
        int h = j >> 2;
        float den = (layer == 0) ? g_denomA[p.y * NH + h]
                                 : g_denomB[p.w * NH + h];
        float alpha = g_ex[(size_t)e * NH + h] / den;
        float4 f  = *(const float4*)(g_feat  + (size_t)p.x * HID + 4 * j);
        float4 rp = *(const float4*)(g_rproj + (size_t)(layer * N_RELS + p.z) * HID + 4 * j);
        float* ob = (layer == 0) ? (g_h1 + (size_t)p.y * HID)
                                 : (dout + (size_t)p.w * HID);
        atomicAdd(ob + 4 * j + 0, (f.x + rp.x) * alpha);
        atomicAdd(ob + 4 * j + 1, (f.y + rp.y) * alpha);
        atomicAdd(ob + 4 * j + 2, (f.z + rp.z) * alpha);
        atomicAdd(ob + 4 * j + 3, (f.w + rp.w) * alpha);
    }
}

// -------- launch --------
extern "C" void kernel_launch(void* const* d_in, const int* in_sizes, int n_in,
                              void* d_out, int out_size) {
    const float* ent_table = (const float*)d_in[0];
    const float* rel_table = (const float*)d_in[1];
    const float* W_ent     = (const float*)d_in[2];
    const float* W_rel     = (const float*)d_in[3];
    const float* attn_l    = (const float*)d_in[4];
    const float* attn_r    = (const float*)d_in[5];
    const float* attn_e    = (const float*)d_in[6];
    const int*   ent_ids   = (const int*)d_in[7];
    const int*   rel_ids   = (const int*)d_in[8];
    const int*   src       = (const int*)d_in[9];
    const int*   dst       = (const int*)d_in[10];
    const int*   goffs     = (const int*)d_in[11];
    float*       out       = (float*)d_out;

    k_init<<<1, 1024>>>(out, goffs);
    k_filter2<<<(N_EDGES / 8 + 255) / 256, 256>>>((const int4*)src, (const int4*)dst, rel_ids);
    k_filter1<<<(N_EDGES / 8 + 255) / 256, 256>>>((const int4*)src, (const int4*)dst, rel_ids);
    k_compact<<<(N_NODES + 255) / 256, 256>>>();
    k_rel<<<2 * N_RELS, 128>>>(rel_table, W_rel, attn_e);

    // layer 0 (full frontier N0)
    k_node<<<2048, 128>>>(0, ent_table, ent_ids, W_ent, attn_l, attn_r);
    k_score<<<512, 256>>>(0);
    k_agg<<<512, 256>>>(0, out);

    // layer 1 (frontier N1, output rows only)
    k_node<<<256, 128>>>(1, ent_table, ent_ids, W_ent, attn_l, attn_r);
    k_score<<<64, 256>>>(1);
    k_agg<<<64, 256>>>(1, out);
}